// round 5
// baseline (speedup 1.0000x reference)
#include <cuda_runtime.h>
#include <cuda_bf16.h>
#include <cuda_fp8.h>
#include <cstdint>

// Problem constants
#define Bb 2
#define Nn 1024
#define Ee 8192
#define Dd 64
#define NT8 8            // 8 tiles of 128 along N
#define PAIRS8 36        // upper-triangular tile pairs
#define KC 64            // K elements per stage
#define KSPLIT 2
#define KHALF (Ee / KSPLIT)        // 4096
#define NCHUNK (KHALF / KC)        // 64

// ---------------------------------------------------------------------------
// Device scratch
// ---------------------------------------------------------------------------
__device__ float g_scale[Bb * Ee];
__device__ float g_hw[Bb * Nn * Dd];
__device__ float g_part[(size_t)Bb * PAIRS8 * KSPLIT * 128 * 128];
__device__ float g_outp8[NT8][Bb * Nn * Dd];
__device__ __nv_bfloat16 g_Ahi[(size_t)Bb * Nn * Ee];
__device__ __nv_bfloat16 g_Bhi[(size_t)Bb * Nn * Ee];
__device__ unsigned char g_A8h[(size_t)Bb * Nn * Ee];   // e4m3(a)
__device__ unsigned char g_A8l[(size_t)Bb * Nn * Ee];   // e4m3(256*(a-ahi))
__device__ unsigned char g_B8h[(size_t)Bb * Nn * Ee];   // e4m3(t)
__device__ unsigned char g_B8l[(size_t)Bb * Nn * Ee];   // e4m3(256*(t-bhi))

// ---------------------------------------------------------------------------
// Portable PTX helpers (sm_80/89-class: cp.async, ldmatrix, mma.sync)
// ---------------------------------------------------------------------------
__device__ __forceinline__ uint32_t smem_u32(const void* p) {
    uint32_t a;
    asm("{ .reg .u64 t; cvta.to.shared.u64 t, %1; cvt.u32.u64 %0, t; }" : "=r"(a) : "l"(p));
    return a;
}
#define CP16(dst, src) \
    asm volatile("cp.async.cg.shared.global [%0], [%1], 16;" :: "r"(dst), "l"(src))
#define CP_COMMIT() asm volatile("cp.async.commit_group;")
#define CP_WAIT0()  asm volatile("cp.async.wait_group 0;")
#define CP_WAIT1()  asm volatile("cp.async.wait_group 1;")
#define SWZ(x) ((x) ^ (((x) >> 3) & 0x70))

__device__ __forceinline__ void ldsm4(uint32_t* r, uint32_t addr) {
    asm volatile("ldmatrix.sync.aligned.m8n8.x4.shared.b16 {%0,%1,%2,%3}, [%4];"
                 : "=r"(r[0]), "=r"(r[1]), "=r"(r[2]), "=r"(r[3]) : "r"(addr));
}
__device__ __forceinline__ void mma16816(float* c, const uint32_t* a, const uint32_t* b) {
    asm volatile(
        "mma.sync.aligned.m16n8k16.row.col.f32.bf16.bf16.f32 "
        "{%0,%1,%2,%3}, {%4,%5,%6,%7}, {%8,%9}, {%0,%1,%2,%3};"
        : "+f"(c[0]), "+f"(c[1]), "+f"(c[2]), "+f"(c[3])
        : "r"(a[0]), "r"(a[1]), "r"(a[2]), "r"(a[3]), "r"(b[0]), "r"(b[1]));
}
__device__ __forceinline__ void mma8(float* c, const uint32_t* a, const uint32_t* b) {
    asm volatile(
        "mma.sync.aligned.m16n8k32.row.col.f32.e4m3.e4m3.f32 "
        "{%0,%1,%2,%3}, {%4,%5,%6,%7}, {%8,%9}, {%0,%1,%2,%3};"
        : "+f"(c[0]), "+f"(c[1]), "+f"(c[2]), "+f"(c[3])
        : "r"(a[0]), "r"(a[1]), "r"(a[2]), "r"(a[3]), "r"(b[0]), "r"(b[1]));
}

// ---------------------------------------------------------------------------
// scale[b,e] = dot(H_e[b,e,:], p)
// ---------------------------------------------------------------------------
__global__ void scale_kernel(const float* __restrict__ H_e,
                             const float* __restrict__ p) {
    __shared__ float ps[64];
    if (threadIdx.x < 64) ps[threadIdx.x] = p[threadIdx.x];
    __syncthreads();
    int r = blockIdx.x * blockDim.x + threadIdx.x;
    if (r < Bb * Ee) {
        const float4* he = reinterpret_cast<const float4*>(H_e + (size_t)r * 64);
        float s = 0.f;
#pragma unroll
        for (int i = 0; i < 16; i++) {
            float4 v = he[i];
            s += v.x * ps[i * 4 + 0] + v.y * ps[i * 4 + 1] +
                 v.z * ps[i * 4 + 2] + v.w * ps[i * 4 + 3];
        }
        g_scale[r] = s;
    }
}

// ---------------------------------------------------------------------------
// prep: split (T*scale) and T into bf16-hi + fp8 arrays
// ---------------------------------------------------------------------------
__global__ void prep_kernel(const float* __restrict__ T) {
    size_t idx8 = ((size_t)blockIdx.x * blockDim.x + threadIdx.x) * 8;
    if (idx8 >= (size_t)Bb * Nn * Ee) return;
    size_t row = idx8 >> 13;
    int e0 = (int)(idx8 & 8191);
    int b = (int)(row >> 10);
    const float4* tp = reinterpret_cast<const float4*>(T + idx8);
    float4 t0 = tp[0], t1 = tp[1];
    const float4* sp = reinterpret_cast<const float4*>(g_scale + b * Ee + e0);
    float4 s0 = sp[0], s1 = sp[1];
    float tv[8] = {t0.x, t0.y, t0.z, t0.w, t1.x, t1.y, t1.z, t1.w};
    float sv[8] = {s0.x, s0.y, s0.z, s0.w, s1.x, s1.y, s1.z, s1.w};
    __align__(16) __nv_bfloat16 ah[8], bh[8];
    __align__(8) unsigned char a8[8], al8[8], b8[8], bl8[8];
#pragma unroll
    for (int i = 0; i < 8; i++) {
        float a = tv[i] * sv[i];
        ah[i] = __float2bfloat16_rn(a);
        float al = a - __bfloat162float(ah[i]);
        bh[i] = __float2bfloat16_rn(tv[i]);
        float bl = tv[i] - __bfloat162float(bh[i]);
        a8[i]  = (unsigned char)__nv_cvt_float_to_fp8(a,          __NV_SATFINITE, __NV_E4M3);
        al8[i] = (unsigned char)__nv_cvt_float_to_fp8(al * 256.f, __NV_SATFINITE, __NV_E4M3);
        b8[i]  = (unsigned char)__nv_cvt_float_to_fp8(tv[i],      __NV_SATFINITE, __NV_E4M3);
        bl8[i] = (unsigned char)__nv_cvt_float_to_fp8(bl * 256.f, __NV_SATFINITE, __NV_E4M3);
    }
    *reinterpret_cast<uint4*>(g_Ahi + idx8) = *reinterpret_cast<uint4*>(ah);
    *reinterpret_cast<uint4*>(g_Bhi + idx8) = *reinterpret_cast<uint4*>(bh);
    *reinterpret_cast<unsigned long long*>(g_A8h + idx8) = *reinterpret_cast<unsigned long long*>(a8);
    *reinterpret_cast<unsigned long long*>(g_A8l + idx8) = *reinterpret_cast<unsigned long long*>(al8);
    *reinterpret_cast<unsigned long long*>(g_B8h + idx8) = *reinterpret_cast<unsigned long long*>(b8);
    *reinterpret_cast<unsigned long long*>(g_B8l + idx8) = *reinterpret_cast<unsigned long long*>(bl8);
}

// ---------------------------------------------------------------------------
// HW[r,d] = dot(H_v[r,:], W[:,d])
// ---------------------------------------------------------------------------
__global__ void hw_kernel(const float* __restrict__ H_v,
                          const float* __restrict__ W) {
    __shared__ float ws[64 * 64];
    __shared__ float hv[4][64];
    int tx = threadIdx.x, ty = threadIdx.y;
    int tid = ty * 64 + tx;
    for (int i = tid; i < 64 * 64; i += 256) ws[i] = W[i];
    int row0 = blockIdx.x * 4;
    hv[ty][tx] = H_v[(size_t)(row0 + ty) * 64 + tx];
    __syncthreads();
    float acc = 0.f;
#pragma unroll
    for (int k = 0; k < 64; k++) acc += hv[ty][k] * ws[k * 64 + tx];
    g_hw[(size_t)(row0 + ty) * 64 + tx] = acc;
}

// ---------------------------------------------------------------------------
// mult partial: 128x128 tile, half-K per CTA
// hi term: bf16 m16n8k16; corrections: e4m3 m16n8k32 (lo pre-scaled x256)
// grid = Bb*PAIRS8*KSPLIT = 144, 256 threads (8 warps, warp grid 2x4)
// ---------------------------------------------------------------------------
#define OFF_AHI 0
#define OFF_BHI 16384
#define OFF_A8H 32768
#define OFF_A8L 43008
#define OFF_B8H 53248
#define OFF_B8L 63488
#define STAGE_BYTES 73728
#define MULT_SMEM (3 * STAGE_BYTES)

__global__ void __launch_bounds__(256, 1)
mult_partial(const float* __restrict__ dummy) {
    extern __shared__ __align__(1024) char smraw[];
    uint32_t stg = smem_u32(smraw);

    int tid = threadIdx.x;
    int wid = tid >> 5;
    int lid = tid & 31;
    int wm = wid & 1;          // m-half (64 rows)
    int wn = wid >> 1;         // n-quarter (32 cols)

    int p2 = blockIdx.x;
    int pair = p2 >> 1;
    int ksp = p2 & 1;
    int b = pair / PAIRS8;
    int t = pair % PAIRS8;
    int ti = 0, rem = t;
    while (rem >= NT8 - ti) { rem -= NT8 - ti; ti++; }
    int tj = ti + rem;

    size_t rowA = (size_t)(b * Nn + ti * 128);
    size_t rowB = (size_t)(b * Nn + tj * 128);
    int kbase = ksp * KHALF;

    auto load_stage = [&](int sidx, int k0) {
        uint32_t sb = stg + sidx * STAGE_BYTES;
#pragma unroll
        for (int i = 0; i < 4; i++) {                // bf16 hi: 1024 chunks each
            int chunk = tid + i * 256;
            int row = chunk >> 3, cc = chunk & 7;
            uint32_t swo = SWZ((uint32_t)(row * 128 + cc * 16));
            CP16(sb + OFF_AHI + swo, g_Ahi + (rowA + row) * (size_t)Ee + k0 + cc * 8);
            CP16(sb + OFF_BHI + swo, g_Bhi + (rowB + row) * (size_t)Ee + k0 + cc * 8);
        }
#pragma unroll
        for (int i = 0; i < 2; i++) {                // fp8: 512 chunks each, 80B rows
            int c2 = tid + i * 256;
            int row = c2 >> 2, cc = c2 & 3;
            uint32_t dof = (uint32_t)(row * 80 + cc * 16);
            size_t ga = (rowA + row) * (size_t)Ee + k0 + cc * 16;
            size_t gb = (rowB + row) * (size_t)Ee + k0 + cc * 16;
            CP16(sb + OFF_A8H + dof, g_A8h + ga);
            CP16(sb + OFF_A8L + dof, g_A8l + ga);
            CP16(sb + OFF_B8H + dof, g_B8h + gb);
            CP16(sb + OFF_B8L + dof, g_B8l + gb);
        }
        CP_COMMIT();
    };

    float acc[4][4][4];
    float acc2[4][4][4];
#pragma unroll
    for (int i = 0; i < 4; i++)
#pragma unroll
        for (int j = 0; j < 4; j++)
#pragma unroll
            for (int q = 0; q < 4; q++) { acc[i][j][q] = 0.f; acc2[i][j][q] = 0.f; }

    load_stage(0, kbase);
    load_stage(1, kbase + KC);

    for (int s = 0; s < NCHUNK; s++) {
        if (s < NCHUNK - 1) CP_WAIT1(); else CP_WAIT0();
        __syncthreads();
        uint32_t sb = stg + (s % 3) * STAGE_BYTES;

#pragma unroll
        for (int ks2 = 0; ks2 < 2; ks2++) {
            // ---- fp8 correction mmas (k32 covers two k16 steps) ----
            {
                uint32_t a8h[4][4], a8l[4][4], b8h[2][4], b8l[2][4];
                uint32_t arow = (uint32_t)((wm * 64 + (lid & 15)) * 80 +
                                           ks2 * 32 + ((lid >> 4) << 4));
#pragma unroll
                for (int mt = 0; mt < 4; mt++) {
                    uint32_t so = arow + (uint32_t)(mt * 16 * 80);
                    ldsm4(a8h[mt], sb + OFF_A8H + so);
                    ldsm4(a8l[mt], sb + OFF_A8L + so);
                }
                uint32_t brow = (uint32_t)((wn * 32 + ((lid >> 4) << 3) + (lid & 7)) * 80 +
                                           ks2 * 32 + (((lid >> 3) & 1) << 4));
#pragma unroll
                for (int nt2 = 0; nt2 < 2; nt2++) {
                    uint32_t so = brow + (uint32_t)(nt2 * 16 * 80);
                    ldsm4(b8h[nt2], sb + OFF_B8H + so);
                    ldsm4(b8l[nt2], sb + OFF_B8L + so);
                }
#pragma unroll
                for (int mt = 0; mt < 4; mt++)
#pragma unroll
                    for (int nt = 0; nt < 4; nt++) {
                        mma8(acc2[mt][nt], a8h[mt], &b8l[nt >> 1][(nt & 1) * 2]);
                        mma8(acc2[mt][nt], a8l[mt], &b8h[nt >> 1][(nt & 1) * 2]);
                    }
            }
            // ---- bf16 hi mmas: two k16 steps ----
#pragma unroll
            for (int ksi = 0; ksi < 2; ksi++) {
                int ks = ks2 * 2 + ksi;
                uint32_t ah[4][4], bh[2][4];
                uint32_t aoff = (uint32_t)((wm * 64 + (lid & 15)) * 128 +
                                           ks * 32 + ((lid >> 4) << 4));
#pragma unroll
                for (int mt = 0; mt < 4; mt++)
                    ldsm4(ah[mt], sb + OFF_AHI + SWZ(aoff + (uint32_t)(mt * 16 * 128)));
                uint32_t boff = (uint32_t)((wn * 32 + ((lid >> 4) << 3) + (lid & 7)) * 128 +
                                           ks * 32 + (((lid >> 3) & 1) << 4));
#pragma unroll
                for (int nt2 = 0; nt2 < 2; nt2++)
                    ldsm4(bh[nt2], sb + OFF_BHI + SWZ(boff + (uint32_t)(nt2 * 16 * 128)));
#pragma unroll
                for (int mt = 0; mt < 4; mt++)
#pragma unroll
                    for (int nt = 0; nt < 4; nt++)
                        mma16816(acc[mt][nt], ah[mt], &bh[nt >> 1][(nt & 1) * 2]);
            }
        }
        if (s + 2 < NCHUNK) load_stage((s + 2) % 3, kbase + (s + 2) * KC);
    }

    // write partial tile: acc + acc2/256
    float* pt = g_part + (size_t)p2 * 128 * 128;
    const float inv256 = 1.f / 256.f;
#pragma unroll
    for (int mt = 0; mt < 4; mt++)
#pragma unroll
        for (int nt = 0; nt < 4; nt++) {
            int r = wm * 64 + mt * 16 + (lid >> 2);
            int c = wn * 32 + nt * 8 + (lid & 3) * 2;
            *reinterpret_cast<float2*>(pt + (size_t)r * 128 + c) =
                make_float2(acc[mt][nt][0] + acc2[mt][nt][0] * inv256,
                            acc[mt][nt][1] + acc2[mt][nt][1] * inv256);
            *reinterpret_cast<float2*>(pt + (size_t)(r + 8) * 128 + c) =
                make_float2(acc[mt][nt][2] + acc2[mt][nt][2] * inv256,
                            acc[mt][nt][3] + acc2[mt][nt][3] * inv256);
        }
}

// ---------------------------------------------------------------------------
// combine_out: per ordered tile (b,i,j): v = mask(part(i,j)) * adj_v;
// out_partial[slot j] [rows i*128..] = v @ HW[j-block]. grid = Bb*64 = 128.
// smem: vs[128][132] (k-major), HWs[128][68]
// ---------------------------------------------------------------------------
#define CO_SMEM (128 * 132 * 4 + 128 * 68 * 4)

__global__ void __launch_bounds__(256, 1)
combine_out(const float* __restrict__ adj_v) {
    extern __shared__ float cs[];
    float* vs = cs;                      // [k][r] stride 132
    float* HWs = cs + 128 * 132;         // [k][d] stride 68

    int tid = threadIdx.x;
    int bid = blockIdx.x;
    int b = bid >> 6;
    int ij = bid & 63;
    int i = ij >> 3, j = ij & 7;

    // HW block j
    const float* HWb = g_hw + (size_t)b * Nn * Dd + (size_t)j * 128 * 64;
    for (int idx = tid; idx < 8192; idx += 256)
        HWs[(idx >> 6) * 68 + (idx & 63)] = HWb[idx];

    // load m tile into vs (k-major).
    int lo = i < j ? i : j, hi = i < j ? j : i;
    int p = 8 * lo - lo * (lo - 1) / 2 + (hi - lo);
    const float* p0 = g_part + ((size_t)(b * PAIRS8 + p) * 2 + 0) * 16384;
    const float* p1 = g_part + ((size_t)(b * PAIRS8 + p) * 2 + 1) * 16384;
    if (i <= j) {
        // stored [r][c]; vs[c][r] = m[r][c]
        for (int idx = tid; idx < 16384; idx += 256) {
            int r = idx >> 7, c = idx & 127;
            vs[c * 132 + r] = p0[idx] + p1[idx];
        }
    } else {
        // need m_ij[r][c] = stored_ji[c][r] -> vs[c][r] = stored_ji[r'][c'] direct copy
        for (int idx = tid; idx < 16384; idx += 256) {
            int rp = idx >> 7, cp = idx & 127;
            vs[rp * 132 + cp] = p0[idx] + p1[idx];
        }
    }
    __syncthreads();

    // mask + adj multiply: element (r,c) of m_ij lives at vs[c][r]
    const float* av = adj_v + (size_t)b * Nn * Nn;
    for (int idx = tid; idx < 16384; idx += 256) {
        int r = idx >> 7, c = idx & 127;
        int n = i * 128 + r, mcol = j * 128 + c;
        float m = vs[c * 132 + r];
        if (i == j && r == c) m = 1.f;
        vs[c * 132 + r] = m * av[(size_t)n * Nn + mcol];
    }
    __syncthreads();

    // GEMM: O[r][d] = sum_k vs[k][r] * HWs[k][d]
    int rq = tid & 15;          // rows rq*8 .. +7
    int cq = tid >> 4;          // cols cq*4 .. +3
    float o[8][4];
#pragma unroll
    for (int r = 0; r < 8; r++)
#pragma unroll
        for (int c = 0; c < 4; c++) o[r][c] = 0.f;

    for (int k = 0; k < 128; k++) {
        float4 h = *reinterpret_cast<float4*>(&HWs[k * 68 + cq * 4]);
        float4 v0 = *reinterpret_cast<float4*>(&vs[k * 132 + rq * 8]);
        float4 v1 = *reinterpret_cast<float4*>(&vs[k * 132 + rq * 8 + 4]);
        float vv[8] = {v0.x, v0.y, v0.z, v0.w, v1.x, v1.y, v1.z, v1.w};
#pragma unroll
        for (int r = 0; r < 8; r++) {
            o[r][0] += vv[r] * h.x; o[r][1] += vv[r] * h.y;
            o[r][2] += vv[r] * h.z; o[r][3] += vv[r] * h.w;
        }
    }

    float* os = g_outp8[j] + ((size_t)b * Nn + i * 128) * 64;
#pragma unroll
    for (int r = 0; r < 8; r++)
        *reinterpret_cast<float4*>(&os[(size_t)(rq * 8 + r) * 64 + cq * 4]) =
            make_float4(o[r][0], o[r][1], o[r][2], o[r][3]);
}

// ---------------------------------------------------------------------------
__global__ void out_reduce(const float* __restrict__ bias, float* __restrict__ out) {
    int idx = blockIdx.x * 256 + threadIdx.x;
    if (idx < Bb * Nn * Dd) {
        float s = bias[idx & 63];
#pragma unroll
        for (int q = 0; q < NT8; q++) s += g_outp8[q][idx];
        out[idx] = s;
    }
}

// ---------------------------------------------------------------------------
extern "C" void kernel_launch(void* const* d_in, const int* in_sizes, int n_in,
                              void* d_out, int out_size) {
    const float* H_v   = (const float*)d_in[0];
    const float* H_e   = (const float*)d_in[1];
    // d_in[2] = adj_e : unused by the reference math
    const float* adj_v = (const float*)d_in[3];
    const float* T     = (const float*)d_in[4];
    const float* W     = (const float*)d_in[5];
    const float* p     = (const float*)d_in[6];
    const float* bias  = (const float*)d_in[7];
    float* out = (float*)d_out;

    static bool attr_set = false;
    if (!attr_set) {
        cudaFuncSetAttribute(mult_partial, cudaFuncAttributeMaxDynamicSharedMemorySize,
                             MULT_SMEM);
        cudaFuncSetAttribute(combine_out, cudaFuncAttributeMaxDynamicSharedMemorySize,
                             CO_SMEM);
        attr_set = true;
    }

    scale_kernel<<<(Bb * Ee + 255) / 256, 256>>>(H_e, p);
    prep_kernel<<<(Bb * Nn * Ee / 8 + 255) / 256, 256>>>(T);
    hw_kernel<<<(Bb * Nn) / 4, dim3(64, 4)>>>(H_v, W);
    mult_partial<<<Bb * PAIRS8 * KSPLIT, 256, MULT_SMEM>>>(nullptr);
    combine_out<<<Bb * NT8 * NT8, 256, CO_SMEM>>>(adj_v);
    out_reduce<<<(Bb * Nn * Dd + 255) / 256, 256>>>(bias, out);

    // Second tuple output: H_e pass-through, appended after `output`
    const long long out_elems = (long long)Bb * Nn * Dd;     // 131072
    const long long he_elems  = (long long)Bb * Ee * 64;     // 1048576
    if ((long long)out_size >= out_elems + he_elems) {
        cudaMemcpyAsync(out + out_elems, H_e,
                        (size_t)he_elems * sizeof(float),
                        cudaMemcpyDeviceToDevice, 0);
    }
}

// round 6
// speedup vs baseline: 1.3267x; 1.3267x over previous
#include <cuda_runtime.h>
#include <cuda_bf16.h>
#include <cstdint>

// Problem constants
#define Bb 2
#define Nn 1024
#define Ee 8192
#define Dd 64
#define NT8 8            // 8 tiles of 128 along N
#define PAIRS8 36        // upper-triangular tile pairs
#define KC 64            // K elements per stage
#define KSPLIT 2
#define KHALF (Ee / KSPLIT)        // 4096
#define NCHUNK (KHALF / KC)        // 64

// ---------------------------------------------------------------------------
// Device scratch
// ---------------------------------------------------------------------------
__device__ float g_scale[Bb * Ee];
__device__ float g_hw[Bb * Nn * Dd];
__device__ float g_part[(size_t)Bb * PAIRS8 * KSPLIT * 128 * 128];
__device__ float g_outp8[NT8][Bb * Nn * Dd];
__device__ float g_Atf[(size_t)Bb * Nn * Ee];   // rna_tf32(T*scale)
__device__ float g_Btf[(size_t)Bb * Nn * Ee];   // rna_tf32(T)

// ---------------------------------------------------------------------------
// Portable PTX helpers
// ---------------------------------------------------------------------------
__device__ __forceinline__ uint32_t smem_u32(const void* p) {
    uint32_t a;
    asm("{ .reg .u64 t; cvta.to.shared.u64 t, %1; cvt.u32.u64 %0, t; }" : "=r"(a) : "l"(p));
    return a;
}
#define CP16(dst, src) \
    asm volatile("cp.async.cg.shared.global [%0], [%1], 16;" :: "r"(dst), "l"(src))
#define CP_COMMIT() asm volatile("cp.async.commit_group;")
#define CP_WAIT0()  asm volatile("cp.async.wait_group 0;")
#define CP_WAIT1()  asm volatile("cp.async.wait_group 1;")

__device__ __forceinline__ uint32_t f2tf32(float x) {
    uint32_t r;
    asm("cvt.rna.tf32.f32 %0, %1;" : "=r"(r) : "f"(x));
    return r;
}
__device__ __forceinline__ void mma_tf32(float* c, const uint32_t* a, const uint32_t* b) {
    asm volatile(
        "mma.sync.aligned.m16n8k8.row.col.f32.tf32.tf32.f32 "
        "{%0,%1,%2,%3}, {%4,%5,%6,%7}, {%8,%9}, {%0,%1,%2,%3};"
        : "+f"(c[0]), "+f"(c[1]), "+f"(c[2]), "+f"(c[3])
        : "r"(a[0]), "r"(a[1]), "r"(a[2]), "r"(a[3]), "r"(b[0]), "r"(b[1]));
}

// ---------------------------------------------------------------------------
// scale[b,e] = dot(H_e[b,e,:], p)
// ---------------------------------------------------------------------------
__global__ void scale_kernel(const float* __restrict__ H_e,
                             const float* __restrict__ p) {
    __shared__ float ps[64];
    if (threadIdx.x < 64) ps[threadIdx.x] = p[threadIdx.x];
    __syncthreads();
    int r = blockIdx.x * blockDim.x + threadIdx.x;
    if (r < Bb * Ee) {
        const float4* he = reinterpret_cast<const float4*>(H_e + (size_t)r * 64);
        float s = 0.f;
#pragma unroll
        for (int i = 0; i < 16; i++) {
            float4 v = he[i];
            s += v.x * ps[i * 4 + 0] + v.y * ps[i * 4 + 1] +
                 v.z * ps[i * 4 + 2] + v.w * ps[i * 4 + 3];
        }
        g_scale[r] = s;
    }
}

// ---------------------------------------------------------------------------
// prep: A = rna_tf32(T*scale), B = rna_tf32(T)  (unbiased tf32 rounding)
// ---------------------------------------------------------------------------
__global__ void prep_kernel(const float* __restrict__ T) {
    size_t idx4 = ((size_t)blockIdx.x * blockDim.x + threadIdx.x) * 4;
    if (idx4 >= (size_t)Bb * Nn * Ee) return;
    size_t row = idx4 >> 13;
    int e0 = (int)(idx4 & 8191);
    int b = (int)(row >> 10);
    float4 t = *reinterpret_cast<const float4*>(T + idx4);
    float4 s = *reinterpret_cast<const float4*>(g_scale + b * Ee + e0);
    uint4 av, bv;
    av.x = f2tf32(t.x * s.x); av.y = f2tf32(t.y * s.y);
    av.z = f2tf32(t.z * s.z); av.w = f2tf32(t.w * s.w);
    bv.x = f2tf32(t.x); bv.y = f2tf32(t.y);
    bv.z = f2tf32(t.z); bv.w = f2tf32(t.w);
    *reinterpret_cast<uint4*>(g_Atf + idx4) = av;
    *reinterpret_cast<uint4*>(g_Btf + idx4) = bv;
}

// ---------------------------------------------------------------------------
// HW[r,d] = dot(H_v[r,:], W[:,d])
// ---------------------------------------------------------------------------
__global__ void hw_kernel(const float* __restrict__ H_v,
                          const float* __restrict__ W) {
    __shared__ float ws[64 * 64];
    __shared__ float hv[4][64];
    int tx = threadIdx.x, ty = threadIdx.y;
    int tid = ty * 64 + tx;
    for (int i = tid; i < 64 * 64; i += 256) ws[i] = W[i];
    int row0 = blockIdx.x * 4;
    hv[ty][tx] = H_v[(size_t)(row0 + ty) * 64 + tx];
    __syncthreads();
    float acc = 0.f;
#pragma unroll
    for (int k = 0; k < 64; k++) acc += hv[ty][k] * ws[k * 64 + tx];
    g_hw[(size_t)(row0 + ty) * 64 + tx] = acc;
}

// ---------------------------------------------------------------------------
// mult partial: 128x128 tile, half-K per CTA, single-term tf32 m16n8k8
// grid = Bb*PAIRS8*KSPLIT = 144, 256 threads (8 warps, warp grid 2x4,
// warp tile 64x32). SMEM: A[128][68] f32 + B[128][68] f32 per stage, 3 stages.
// Stride 68 words -> conflict-free scalar LDS for all fragment loads.
// ---------------------------------------------------------------------------
#define STRIDE_W 68
#define STAGE_WORDS (128 * STRIDE_W)           // per array: 8704 words
#define OFF_B_BYTES (STAGE_WORDS * 4)          // 34816
#define STAGE_BYTES (2 * STAGE_WORDS * 4)      // 69632
#define MULT_SMEM (3 * STAGE_BYTES)            // 208896

__global__ void __launch_bounds__(256, 1)
mult_partial(const float* __restrict__ dummy) {
    extern __shared__ __align__(16) char smraw[];
    uint32_t stg = smem_u32(smraw);
    const uint32_t* smw = reinterpret_cast<const uint32_t*>(smraw);

    int tid = threadIdx.x;
    int wid = tid >> 5;
    int lid = tid & 31;
    int wm = wid & 1;          // m-half (64 rows)
    int wn = wid >> 1;         // n-quarter (32 cols)

    int p2 = blockIdx.x;
    int pair = p2 >> 1;
    int ksp = p2 & 1;
    int b = pair / PAIRS8;
    int t = pair % PAIRS8;
    int ti = 0, rem = t;
    while (rem >= NT8 - ti) { rem -= NT8 - ti; ti++; }
    int tj = ti + rem;

    size_t rowA = (size_t)(b * Nn + ti * 128);
    size_t rowB = (size_t)(b * Nn + tj * 128);
    int kbase = ksp * KHALF;

    auto load_stage = [&](int sidx, int k0) {
        uint32_t sb = stg + sidx * STAGE_BYTES;
#pragma unroll
        for (int i = 0; i < 8; i++) {
            int chunk = tid + i * 256;           // 0..2047
            int row = chunk >> 4, cc = chunk & 15;
            uint32_t d = (uint32_t)(row * (STRIDE_W * 4) + cc * 16);
            CP16(sb + d, g_Atf + (rowA + row) * (size_t)Ee + k0 + cc * 4);
            CP16(sb + OFF_B_BYTES + d, g_Btf + (rowB + row) * (size_t)Ee + k0 + cc * 4);
        }
        CP_COMMIT();
    };

    float acc[4][4][4];
#pragma unroll
    for (int i = 0; i < 4; i++)
#pragma unroll
        for (int j = 0; j < 4; j++)
#pragma unroll
            for (int q = 0; q < 4; q++) acc[i][j][q] = 0.f;

    load_stage(0, kbase);
    load_stage(1, kbase + KC);

    int lrow = lid >> 2;       // 0..7
    int lcol = lid & 3;        // 0..3

    for (int s = 0; s < NCHUNK; s++) {
        if (s < NCHUNK - 1) CP_WAIT1(); else CP_WAIT0();
        __syncthreads();
        const uint32_t* As = smw + (s % 3) * (STAGE_BYTES / 4);
        const uint32_t* Bs = As + STAGE_WORDS;

#pragma unroll
        for (int ks = 0; ks < 8; ks++) {
            int kc = ks * 8 + lcol;
            uint32_t af[4][4], bf[4][2];
#pragma unroll
            for (int mt = 0; mt < 4; mt++) {
                int rb = (wm * 64 + mt * 16 + lrow) * STRIDE_W;
                af[mt][0] = As[rb + kc];
                af[mt][1] = As[rb + 8 * STRIDE_W + kc];
                af[mt][2] = As[rb + kc + 4];
                af[mt][3] = As[rb + 8 * STRIDE_W + kc + 4];
            }
#pragma unroll
            for (int nt = 0; nt < 4; nt++) {
                int nb = (wn * 32 + nt * 8 + lrow) * STRIDE_W;
                bf[nt][0] = Bs[nb + kc];
                bf[nt][1] = Bs[nb + kc + 4];
            }
#pragma unroll
            for (int mt = 0; mt < 4; mt++)
#pragma unroll
                for (int nt = 0; nt < 4; nt++)
                    mma_tf32(acc[mt][nt], af[mt], bf[nt]);
        }
        if (s + 2 < NCHUNK) load_stage((s + 2) % 3, kbase + (s + 2) * KC);
    }

    // write partial tile
    float* pt = g_part + (size_t)p2 * 128 * 128;
#pragma unroll
    for (int mt = 0; mt < 4; mt++)
#pragma unroll
        for (int nt = 0; nt < 4; nt++) {
            int r = wm * 64 + mt * 16 + (lid >> 2);
            int c = wn * 32 + nt * 8 + (lid & 3) * 2;
            *reinterpret_cast<float2*>(pt + (size_t)r * 128 + c) =
                make_float2(acc[mt][nt][0], acc[mt][nt][1]);
            *reinterpret_cast<float2*>(pt + (size_t)(r + 8) * 128 + c) =
                make_float2(acc[mt][nt][2], acc[mt][nt][3]);
        }
}

// ---------------------------------------------------------------------------
// combine_out: per ordered tile (b,i,j): v = mask(part(i,j)) * adj_v;
// out_partial[slot j][rows i*128..] = v @ HW[j-block]. grid = Bb*64 = 128.
// smem: vs[128][132] (k-major), HWs[128][68]
// ---------------------------------------------------------------------------
#define CO_SMEM (128 * 132 * 4 + 128 * 68 * 4)

__global__ void __launch_bounds__(256, 1)
combine_out(const float* __restrict__ adj_v) {
    extern __shared__ float cs[];
    float* vs = cs;                      // [k][r] stride 132
    float* HWs = cs + 128 * 132;         // [k][d] stride 68

    int tid = threadIdx.x;
    int bid = blockIdx.x;
    int b = bid >> 6;
    int ij = bid & 63;
    int i = ij >> 3, j = ij & 7;

    const float* HWb = g_hw + (size_t)b * Nn * Dd + (size_t)j * 128 * 64;
    for (int idx = tid; idx < 8192; idx += 256)
        HWs[(idx >> 6) * 68 + (idx & 63)] = HWb[idx];

    int lo = i < j ? i : j, hi = i < j ? j : i;
    int p = 8 * lo - lo * (lo - 1) / 2 + (hi - lo);
    const float* p0 = g_part + ((size_t)(b * PAIRS8 + p) * 2 + 0) * 16384;
    const float* p1 = g_part + ((size_t)(b * PAIRS8 + p) * 2 + 1) * 16384;
    if (i <= j) {
        for (int idx = tid; idx < 16384; idx += 256) {
            int r = idx >> 7, c = idx & 127;
            vs[c * 132 + r] = p0[idx] + p1[idx];
        }
    } else {
        for (int idx = tid; idx < 16384; idx += 256) {
            int rp = idx >> 7, cp = idx & 127;
            vs[rp * 132 + cp] = p0[idx] + p1[idx];
        }
    }
    __syncthreads();

    const float* av = adj_v + (size_t)b * Nn * Nn;
    for (int idx = tid; idx < 16384; idx += 256) {
        int r = idx >> 7, c = idx & 127;
        int n = i * 128 + r, mcol = j * 128 + c;
        float m = vs[c * 132 + r];
        if (i == j && r == c) m = 1.f;
        vs[c * 132 + r] = m * av[(size_t)n * Nn + mcol];
    }
    __syncthreads();

    int rq = tid & 15;          // rows rq*8 .. +7
    int cq = tid >> 4;          // cols cq*4 .. +3
    float o[8][4];
#pragma unroll
    for (int r = 0; r < 8; r++)
#pragma unroll
        for (int c = 0; c < 4; c++) o[r][c] = 0.f;

    for (int k = 0; k < 128; k++) {
        float4 h = *reinterpret_cast<float4*>(&HWs[k * 68 + cq * 4]);
        float4 v0 = *reinterpret_cast<float4*>(&vs[k * 132 + rq * 8]);
        float4 v1 = *reinterpret_cast<float4*>(&vs[k * 132 + rq * 8 + 4]);
        float vv[8] = {v0.x, v0.y, v0.z, v0.w, v1.x, v1.y, v1.z, v1.w};
#pragma unroll
        for (int r = 0; r < 8; r++) {
            o[r][0] += vv[r] * h.x; o[r][1] += vv[r] * h.y;
            o[r][2] += vv[r] * h.z; o[r][3] += vv[r] * h.w;
        }
    }

    float* os = g_outp8[j] + ((size_t)b * Nn + i * 128) * 64;
#pragma unroll
    for (int r = 0; r < 8; r++)
        *reinterpret_cast<float4*>(&os[(size_t)(rq * 8 + r) * 64 + cq * 4]) =
            make_float4(o[r][0], o[r][1], o[r][2], o[r][3]);
}

// ---------------------------------------------------------------------------
__global__ void out_reduce(const float* __restrict__ bias, float* __restrict__ out) {
    int idx = blockIdx.x * 256 + threadIdx.x;
    if (idx < Bb * Nn * Dd) {
        float s = bias[idx & 63];
#pragma unroll
        for (int q = 0; q < NT8; q++) s += g_outp8[q][idx];
        out[idx] = s;
    }
}

// ---------------------------------------------------------------------------
extern "C" void kernel_launch(void* const* d_in, const int* in_sizes, int n_in,
                              void* d_out, int out_size) {
    const float* H_v   = (const float*)d_in[0];
    const float* H_e   = (const float*)d_in[1];
    // d_in[2] = adj_e : unused by the reference math
    const float* adj_v = (const float*)d_in[3];
    const float* T     = (const float*)d_in[4];
    const float* W     = (const float*)d_in[5];
    const float* p     = (const float*)d_in[6];
    const float* bias  = (const float*)d_in[7];
    float* out = (float*)d_out;

    static bool attr_set = false;
    if (!attr_set) {
        cudaFuncSetAttribute(mult_partial, cudaFuncAttributeMaxDynamicSharedMemorySize,
                             MULT_SMEM);
        cudaFuncSetAttribute(combine_out, cudaFuncAttributeMaxDynamicSharedMemorySize,
                             CO_SMEM);
        attr_set = true;
    }

    scale_kernel<<<(Bb * Ee + 255) / 256, 256>>>(H_e, p);
    prep_kernel<<<(Bb * Nn * Ee / 4 + 255) / 256, 256>>>(T);
    hw_kernel<<<(Bb * Nn) / 4, dim3(64, 4)>>>(H_v, W);
    mult_partial<<<Bb * PAIRS8 * KSPLIT, 256, MULT_SMEM>>>(nullptr);
    combine_out<<<Bb * NT8 * NT8, 256, CO_SMEM>>>(adj_v);
    out_reduce<<<(Bb * Nn * Dd + 255) / 256, 256>>>(bias, out);

    // Second tuple output: H_e pass-through, appended after `output`
    const long long out_elems = (long long)Bb * Nn * Dd;     // 131072
    const long long he_elems  = (long long)Bb * Ee * 64;     // 1048576
    if ((long long)out_size >= out_elems + he_elems) {
        cudaMemcpyAsync(out + out_elems, H_e,
                        (size_t)he_elems * sizeof(float),
                        cudaMemcpyDeviceToDevice, 0);
    }
}

// round 9
// speedup vs baseline: 1.3552x; 1.0215x over previous
#include <cuda_runtime.h>
#include <cuda_bf16.h>
#include <cstdint>

// Problem constants
#define Bb 2
#define Nn 1024
#define Ee 8192
#define Dd 64
#define NT8 8            // 8 tiles of 128 along N
#define PAIRS8 36        // upper-triangular tile pairs
#define KC 32            // K elements per stage
#define KSPLIT 4
#define KQ (Ee / KSPLIT)           // 2048
#define NCHUNK (KQ / KC)           // 64

// ---------------------------------------------------------------------------
// Device scratch
// ---------------------------------------------------------------------------
__device__ float g_scale[Bb * Ee];
__device__ float g_hw[Bb * Nn * Dd];
__device__ float g_part[(size_t)Bb * PAIRS8 * KSPLIT * 128 * 128];
__device__ float g_outp8[NT8][Bb * Nn * Dd];
__device__ float g_Atf[(size_t)Bb * Nn * Ee];   // rna_tf32(T*scale)
__device__ float g_Btf[(size_t)Bb * Nn * Ee];   // rna_tf32(T)

// ---------------------------------------------------------------------------
// Portable PTX helpers
// ---------------------------------------------------------------------------
__device__ __forceinline__ uint32_t smem_u32(const void* p) {
    uint32_t a;
    asm("{ .reg .u64 t; cvta.to.shared.u64 t, %1; cvt.u32.u64 %0, t; }" : "=r"(a) : "l"(p));
    return a;
}
#define CP16(dst, src) \
    asm volatile("cp.async.cg.shared.global [%0], [%1], 16;" :: "r"(dst), "l"(src))
#define CP_COMMIT() asm volatile("cp.async.commit_group;")
#define CP_WAIT0()  asm volatile("cp.async.wait_group 0;")
#define CP_WAIT1()  asm volatile("cp.async.wait_group 1;")

__device__ __forceinline__ uint32_t f2tf32(float x) {
    uint32_t r;
    asm("cvt.rna.tf32.f32 %0, %1;" : "=r"(r) : "f"(x));
    return r;
}
__device__ __forceinline__ void mma_tf32(float* c, const uint32_t* a, const uint32_t* b) {
    asm volatile(
        "mma.sync.aligned.m16n8k8.row.col.f32.tf32.tf32.f32 "
        "{%0,%1,%2,%3}, {%4,%5,%6,%7}, {%8,%9}, {%0,%1,%2,%3};"
        : "+f"(c[0]), "+f"(c[1]), "+f"(c[2]), "+f"(c[3])
        : "r"(a[0]), "r"(a[1]), "r"(a[2]), "r"(a[3]), "r"(b[0]), "r"(b[1]));
}

// ---------------------------------------------------------------------------
// scale[b,e] = dot(H_e[b,e,:], p)
// ---------------------------------------------------------------------------
__global__ void scale_kernel(const float* __restrict__ H_e,
                             const float* __restrict__ p) {
    __shared__ float ps[64];
    if (threadIdx.x < 64) ps[threadIdx.x] = p[threadIdx.x];
    __syncthreads();
    int r = blockIdx.x * blockDim.x + threadIdx.x;
    if (r < Bb * Ee) {
        const float4* he = reinterpret_cast<const float4*>(H_e + (size_t)r * 64);
        float s = 0.f;
#pragma unroll
        for (int i = 0; i < 16; i++) {
            float4 v = he[i];
            s += v.x * ps[i * 4 + 0] + v.y * ps[i * 4 + 1] +
                 v.z * ps[i * 4 + 2] + v.w * ps[i * 4 + 3];
        }
        g_scale[r] = s;
    }
}

// ---------------------------------------------------------------------------
// prep: A = rna_tf32(T*scale), B = rna_tf32(T)
// ---------------------------------------------------------------------------
__global__ void prep_kernel(const float* __restrict__ T) {
    size_t idx4 = ((size_t)blockIdx.x * blockDim.x + threadIdx.x) * 4;
    if (idx4 >= (size_t)Bb * Nn * Ee) return;
    size_t row = idx4 >> 13;
    int e0 = (int)(idx4 & 8191);
    int b = (int)(row >> 10);
    float4 t = *reinterpret_cast<const float4*>(T + idx4);
    float4 s = *reinterpret_cast<const float4*>(g_scale + b * Ee + e0);
    uint4 av, bv;
    av.x = f2tf32(t.x * s.x); av.y = f2tf32(t.y * s.y);
    av.z = f2tf32(t.z * s.z); av.w = f2tf32(t.w * s.w);
    bv.x = f2tf32(t.x); bv.y = f2tf32(t.y);
    bv.z = f2tf32(t.z); bv.w = f2tf32(t.w);
    *reinterpret_cast<uint4*>(g_Atf + idx4) = av;
    *reinterpret_cast<uint4*>(g_Btf + idx4) = bv;
}

// ---------------------------------------------------------------------------
// HW[r,d] = dot(H_v[r,:], W[:,d])
// ---------------------------------------------------------------------------
__global__ void hw_kernel(const float* __restrict__ H_v,
                          const float* __restrict__ W) {
    __shared__ float ws[64 * 64];
    __shared__ float hv[4][64];
    int tx = threadIdx.x, ty = threadIdx.y;
    int tid = ty * 64 + tx;
    for (int i = tid; i < 64 * 64; i += 256) ws[i] = W[i];
    int row0 = blockIdx.x * 4;
    hv[ty][tx] = H_v[(size_t)(row0 + ty) * 64 + tx];
    __syncthreads();
    float acc = 0.f;
#pragma unroll
    for (int k = 0; k < 64; k++) acc += hv[ty][k] * ws[k * 64 + tx];
    g_hw[(size_t)(row0 + ty) * 64 + tx] = acc;
}

// ---------------------------------------------------------------------------
// mult partial: 128x128 tile, quarter-K per CTA, single-term tf32 m16n8k8
// grid = Bb*PAIRS8*KSPLIT = 288 (~2 CTAs/SM), 256 threads, warp grid 2x4.
// SMEM: A[128][36] f32 + B[128][36] f32 per stage, 3 stages = 108 KB
// -> 2 CTAs resident per SM. Stride 36 words keeps scalar LDS conflict-free
// (bank = (lrow*36 + lcol) % 32 = lid).
// ---------------------------------------------------------------------------
#define STRIDE_W 36
#define STAGE_WORDS (128 * STRIDE_W)           // per array: 4608 words
#define OFF_B_BYTES (STAGE_WORDS * 4)          // 18432
#define STAGE_BYTES (2 * STAGE_WORDS * 4)      // 36864
#define MULT_SMEM (3 * STAGE_BYTES)            // 110592

__global__ void __launch_bounds__(256, 2)
mult_partial(const float* __restrict__ dummy) {
    extern __shared__ __align__(16) char smraw[];
    uint32_t stg = smem_u32(smraw);
    const uint32_t* smw = reinterpret_cast<const uint32_t*>(smraw);

    int tid = threadIdx.x;
    int wid = tid >> 5;
    int lid = tid & 31;
    int wm = wid & 1;          // m-half (64 rows)
    int wn = wid >> 1;         // n-quarter (32 cols)

    int p2 = blockIdx.x;
    int pair = p2 >> 2;
    int ksp = p2 & 3;
    int b = pair / PAIRS8;
    int t = pair % PAIRS8;
    int ti = 0, rem = t;
    while (rem >= NT8 - ti) { rem -= NT8 - ti; ti++; }
    int tj = ti + rem;

    size_t rowA = (size_t)(b * Nn + ti * 128);
    size_t rowB = (size_t)(b * Nn + tj * 128);
    int kbase = ksp * KQ;

    auto load_stage = [&](int sidx, int k0) {
        uint32_t sb = stg + sidx * STAGE_BYTES;
#pragma unroll
        for (int i = 0; i < 4; i++) {
            int chunk = tid + i * 256;           // 0..1023
            int row = chunk >> 3, cc = chunk & 7;
            uint32_t d = (uint32_t)(row * (STRIDE_W * 4) + cc * 16);
            CP16(sb + d, g_Atf + (rowA + row) * (size_t)Ee + k0 + cc * 4);
            CP16(sb + OFF_B_BYTES + d, g_Btf + (rowB + row) * (size_t)Ee + k0 + cc * 4);
        }
        CP_COMMIT();
    };

    float acc[4][4][4];
#pragma unroll
    for (int i = 0; i < 4; i++)
#pragma unroll
        for (int j = 0; j < 4; j++)
#pragma unroll
            for (int q = 0; q < 4; q++) acc[i][j][q] = 0.f;

    load_stage(0, kbase);
    load_stage(1, kbase + KC);

    int lrow = lid >> 2;       // 0..7
    int lcol = lid & 3;        // 0..3

    for (int s = 0; s < NCHUNK; s++) {
        if (s < NCHUNK - 1) CP_WAIT1(); else CP_WAIT0();
        __syncthreads();
        const uint32_t* As = smw + (s % 3) * (STAGE_BYTES / 4);
        const uint32_t* Bs = As + STAGE_WORDS;

#pragma unroll
        for (int ks = 0; ks < 4; ks++) {
            int kc = ks * 8 + lcol;
            uint32_t af[4][4], bf[4][2];
#pragma unroll
            for (int mt = 0; mt < 4; mt++) {
                int rb = (wm * 64 + mt * 16 + lrow) * STRIDE_W;
                af[mt][0] = As[rb + kc];
                af[mt][1] = As[rb + 8 * STRIDE_W + kc];
                af[mt][2] = As[rb + kc + 4];
                af[mt][3] = As[rb + 8 * STRIDE_W + kc + 4];
            }
#pragma unroll
            for (int nt = 0; nt < 4; nt++) {
                int nb = (wn * 32 + nt * 8 + lrow) * STRIDE_W;
                bf[nt][0] = Bs[nb + kc];
                bf[nt][1] = Bs[nb + kc + 4];
            }
#pragma unroll
            for (int mt = 0; mt < 4; mt++)
#pragma unroll
                for (int nt = 0; nt < 4; nt++)
                    mma_tf32(acc[mt][nt], af[mt], bf[nt]);
        }
        if (s + 2 < NCHUNK) load_stage((s + 2) % 3, kbase + (s + 2) * KC);
    }

    // write partial tile
    float* pt = g_part + (size_t)p2 * 128 * 128;
#pragma unroll
    for (int mt = 0; mt < 4; mt++)
#pragma unroll
        for (int nt = 0; nt < 4; nt++) {
            int r = wm * 64 + mt * 16 + (lid >> 2);
            int c = wn * 32 + nt * 8 + (lid & 3) * 2;
            *reinterpret_cast<float2*>(pt + (size_t)r * 128 + c) =
                make_float2(acc[mt][nt][0], acc[mt][nt][1]);
            *reinterpret_cast<float2*>(pt + (size_t)(r + 8) * 128 + c) =
                make_float2(acc[mt][nt][2], acc[mt][nt][3]);
        }
}

// ---------------------------------------------------------------------------
// combine_out: per ordered tile (b,i,j): v = mask(sum of 4 partials) * adj_v;
// out_partial[slot j][rows i*128..] = v @ HW[j-block]. grid = Bb*64 = 128.
// ---------------------------------------------------------------------------
#define CO_SMEM (128 * 132 * 4 + 128 * 68 * 4)

__global__ void __launch_bounds__(256, 1)
combine_out(const float* __restrict__ adj_v) {
    extern __shared__ float cs[];
    float* vs = cs;                      // [k][r] stride 132
    float* HWs = cs + 128 * 132;         // [k][d] stride 68

    int tid = threadIdx.x;
    int bid = blockIdx.x;
    int b = bid >> 6;
    int ij = bid & 63;
    int i = ij >> 3, j = ij & 7;

    const float* HWb = g_hw + (size_t)b * Nn * Dd + (size_t)j * 128 * 64;
    for (int idx = tid; idx < 8192; idx += 256)
        HWs[(idx >> 6) * 68 + (idx & 63)] = HWb[idx];

    int lo = i < j ? i : j, hi = i < j ? j : i;
    int p = 8 * lo - lo * (lo - 1) / 2 + (hi - lo);
    const float* p0 = g_part + ((size_t)(b * PAIRS8 + p) * 4 + 0) * 16384;
    const float* p1 = g_part + ((size_t)(b * PAIRS8 + p) * 4 + 1) * 16384;
    const float* p2 = g_part + ((size_t)(b * PAIRS8 + p) * 4 + 2) * 16384;
    const float* p3 = g_part + ((size_t)(b * PAIRS8 + p) * 4 + 3) * 16384;
    if (i <= j) {
        for (int idx = tid; idx < 16384; idx += 256) {
            int r = idx >> 7, c = idx & 127;
            vs[c * 132 + r] = (p0[idx] + p1[idx]) + (p2[idx] + p3[idx]);
        }
    } else {
        for (int idx = tid; idx < 16384; idx += 256) {
            int rp = idx >> 7, cp = idx & 127;
            vs[rp * 132 + cp] = (p0[idx] + p1[idx]) + (p2[idx] + p3[idx]);
        }
    }
    __syncthreads();

    const float* av = adj_v + (size_t)b * Nn * Nn;
    for (int idx = tid; idx < 16384; idx += 256) {
        int r = idx >> 7, c = idx & 127;
        int n = i * 128 + r, mcol = j * 128 + c;
        float m = vs[c * 132 + r];
        if (i == j && r == c) m = 1.f;
        vs[c * 132 + r] = m * av[(size_t)n * Nn + mcol];
    }
    __syncthreads();

    int rq = tid & 15;          // rows rq*8 .. +7
    int cq = tid >> 4;          // cols cq*4 .. +3
    float o[8][4];
#pragma unroll
    for (int r = 0; r < 8; r++)
#pragma unroll
        for (int c = 0; c < 4; c++) o[r][c] = 0.f;

    for (int k = 0; k < 128; k++) {
        float4 h = *reinterpret_cast<float4*>(&HWs[k * 68 + cq * 4]);
        float4 v0 = *reinterpret_cast<float4*>(&vs[k * 132 + rq * 8]);
        float4 v1 = *reinterpret_cast<float4*>(&vs[k * 132 + rq * 8 + 4]);
        float vv[8] = {v0.x, v0.y, v0.z, v0.w, v1.x, v1.y, v1.z, v1.w};
#pragma unroll
        for (int r = 0; r < 8; r++) {
            o[r][0] += vv[r] * h.x; o[r][1] += vv[r] * h.y;
            o[r][2] += vv[r] * h.z; o[r][3] += vv[r] * h.w;
        }
    }

    float* os = g_outp8[j] + ((size_t)b * Nn + i * 128) * 64;
#pragma unroll
    for (int r = 0; r < 8; r++)
        *reinterpret_cast<float4*>(&os[(size_t)(rq * 8 + r) * 64 + cq * 4]) =
            make_float4(o[r][0], o[r][1], o[r][2], o[r][3]);
}

// ---------------------------------------------------------------------------
__global__ void out_reduce(const float* __restrict__ bias, float* __restrict__ out) {
    int idx = blockIdx.x * 256 + threadIdx.x;
    if (idx < Bb * Nn * Dd) {
        float s = bias[idx & 63];
#pragma unroll
        for (int q = 0; q < NT8; q++) s += g_outp8[q][idx];
        out[idx] = s;
    }
}

// ---------------------------------------------------------------------------
extern "C" void kernel_launch(void* const* d_in, const int* in_sizes, int n_in,
                              void* d_out, int out_size) {
    const float* H_v   = (const float*)d_in[0];
    const float* H_e   = (const float*)d_in[1];
    // d_in[2] = adj_e : unused by the reference math
    const float* adj_v = (const float*)d_in[3];
    const float* T     = (const float*)d_in[4];
    const float* W     = (const float*)d_in[5];
    const float* p     = (const float*)d_in[6];
    const float* bias  = (const float*)d_in[7];
    float* out = (float*)d_out;

    static bool attr_set = false;
    if (!attr_set) {
        cudaFuncSetAttribute(mult_partial, cudaFuncAttributeMaxDynamicSharedMemorySize,
                             MULT_SMEM);
        cudaFuncSetAttribute(combine_out, cudaFuncAttributeMaxDynamicSharedMemorySize,
                             CO_SMEM);
        attr_set = true;
    }

    scale_kernel<<<(Bb * Ee + 255) / 256, 256>>>(H_e, p);
    prep_kernel<<<(Bb * Nn * Ee / 4 + 255) / 256, 256>>>(T);
    hw_kernel<<<(Bb * Nn) / 4, dim3(64, 4)>>>(H_v, W);
    mult_partial<<<Bb * PAIRS8 * KSPLIT, 256, MULT_SMEM>>>(nullptr);
    combine_out<<<Bb * NT8 * NT8, 256, CO_SMEM>>>(adj_v);
    out_reduce<<<(Bb * Nn * Dd + 255) / 256, 256>>>(bias, out);

    // Second tuple output: H_e pass-through, appended after `output`
    const long long out_elems = (long long)Bb * Nn * Dd;     // 131072
    const long long he_elems  = (long long)Bb * Ee * 64;     // 1048576
    if ((long long)out_size >= out_elems + he_elems) {
        cudaMemcpyAsync(out + out_elems, H_e,
                        (size_t)he_elems * sizeof(float),
                        cudaMemcpyDeviceToDevice, 0);
    }
}